// round 10
// baseline (speedup 1.0000x reference)
#include <cuda_runtime.h>
#include <cuda_bf16.h>
#include <cstdint>

// ---------------------------------------------------------------------------
// Problem: B=4, S=2048, D=1024
//   Q = q_in @ Wq^T + bq ; K = k_in @ Wk^T + bk ; V = v_in @ Wv^T + bv
//   Sc = relu(Q @ K^T) per batch ;  O = Sc @ V per batch
// All GEMMs on mma.sync.m16n8k16 bf16 tensor cores with 2-term bf16 operand
// splitting (hi*hi + hi*lo + lo*hi) for fp32-class accuracy.
// R9: 512 threads / 16 warps per CTA, warp tile 64x32 (occupancy 12.5->25%).
// ---------------------------------------------------------------------------

#define BATCH 4
#define SEQ   2048
#define DIM   1024

#define BM 128
#define BN 256
#define KC 64                       // bf16 per K chunk = 128 bytes/row
#define THREADS 512

#define TILE_A_BYTES (BM * 128)     // 16 KB per split
#define TILE_B_BYTES (BN * 128)     // 32 KB per split
#define OFF_AH 0
#define OFF_AL (TILE_A_BYTES)
#define OFF_BH (2 * TILE_A_BYTES)
#define OFF_BL (2 * TILE_A_BYTES + TILE_B_BYTES)
#define STAGE_BYTES (2 * TILE_A_BYTES + 2 * TILE_B_BYTES)   // 96 KB
#define SMEM_TOTAL (2 * STAGE_BYTES)                        // 192 KB

#define EP_LD 260                   // epilogue smem row stride (u32)

// ---------------- device-global scratch (no allocations allowed) -----------
__device__ __nv_bfloat16 g_qi_h[(size_t)BATCH * SEQ * DIM];
__device__ __nv_bfloat16 g_qi_l[(size_t)BATCH * SEQ * DIM];
__device__ __nv_bfloat16 g_ki_h[(size_t)BATCH * SEQ * DIM];
__device__ __nv_bfloat16 g_ki_l[(size_t)BATCH * SEQ * DIM];
__device__ __nv_bfloat16 g_vi_h[(size_t)BATCH * SEQ * DIM];
__device__ __nv_bfloat16 g_vi_l[(size_t)BATCH * SEQ * DIM];
__device__ __nv_bfloat16 g_wq_h[(size_t)DIM * DIM];
__device__ __nv_bfloat16 g_wq_l[(size_t)DIM * DIM];
__device__ __nv_bfloat16 g_wk_h[(size_t)DIM * DIM];
__device__ __nv_bfloat16 g_wk_l[(size_t)DIM * DIM];
__device__ __nv_bfloat16 g_wv_h[(size_t)DIM * DIM];
__device__ __nv_bfloat16 g_wv_l[(size_t)DIM * DIM];
__device__ __nv_bfloat16 g_Q_h[(size_t)BATCH * SEQ * DIM];
__device__ __nv_bfloat16 g_Q_l[(size_t)BATCH * SEQ * DIM];
__device__ __nv_bfloat16 g_K_h[(size_t)BATCH * SEQ * DIM];
__device__ __nv_bfloat16 g_K_l[(size_t)BATCH * SEQ * DIM];
__device__ __nv_bfloat16 g_Vt_h[(size_t)BATCH * DIM * SEQ];   // [b][d][s]
__device__ __nv_bfloat16 g_Vt_l[(size_t)BATCH * DIM * SEQ];
__device__ __nv_bfloat16 g_S_h[(size_t)BATCH * SEQ * SEQ];
__device__ __nv_bfloat16 g_S_l[(size_t)BATCH * SEQ * SEQ];

// ----------------------------- asm helpers --------------------------------
__device__ __forceinline__ uint32_t smem_u32(const void* p) {
    uint32_t a;
    asm("{ .reg .u64 t; cvta.to.shared.u64 t, %1; cvt.u32.u64 %0, t; }"
        : "=r"(a) : "l"(p));
    return a;
}

__device__ __forceinline__ void cp16(uint32_t dst, const void* src) {
    asm volatile("cp.async.cg.shared.global [%0], [%1], 16;" :: "r"(dst), "l"(src));
}

#define LDSM4(r, addr) \
    asm volatile("ldmatrix.sync.aligned.m8n8.x4.shared.b16 {%0,%1,%2,%3}, [%4];" \
        : "=r"((r)[0]), "=r"((r)[1]), "=r"((r)[2]), "=r"((r)[3]) : "r"(addr))

#define MMA(c, a, b0, b1) \
    asm volatile("mma.sync.aligned.m16n8k16.row.col.f32.bf16.bf16.f32 " \
        "{%0,%1,%2,%3}, {%4,%5,%6,%7}, {%8,%9}, {%0,%1,%2,%3};" \
        : "+f"((c)[0]), "+f"((c)[1]), "+f"((c)[2]), "+f"((c)[3]) \
        : "r"((a)[0]), "r"((a)[1]), "r"((a)[2]), "r"((a)[3]), "r"(b0), "r"(b1))

// Load one stage: A(hi,lo) 128x64 bf16 + B(hi,lo) 256x64 bf16 (96 KB).
// Smem layout per split: row*128B, 16B chunk c16 swizzled by (c16 ^ (row&7)).
__device__ __forceinline__ void load_stage(
    uint32_t sb,
    const __nv_bfloat16* __restrict__ Ah, const __nv_bfloat16* __restrict__ Al,
    const __nv_bfloat16* __restrict__ Bh, const __nv_bfloat16* __restrict__ Bl,
    int bm, int bn, int K, int kt, int tid)
{
#pragma unroll
    for (int it = 0; it < 12; it++) {
        int lin = it * THREADS + tid;
        const __nv_bfloat16* gp;
        uint32_t toff;
        int c;
        if (it < 2)       { c = lin;        gp = Ah + (long long)(bm + (c >> 3)) * K; toff = OFF_AH; }
        else if (it < 4)  { c = lin - 1024; gp = Al + (long long)(bm + (c >> 3)) * K; toff = OFF_AL; }
        else if (it < 8)  { c = lin - 2048; gp = Bh + (long long)(bn + (c >> 3)) * K; toff = OFF_BH; }
        else              { c = lin - 4096; gp = Bl + (long long)(bn + (c >> 3)) * K; toff = OFF_BL; }
        int row = c >> 3;
        int c16 = c & 7;
        uint32_t dst = sb + toff + (uint32_t)row * 128u +
                       (uint32_t)((c16 ^ (row & 7)) << 4);
        cp16(dst, gp + kt + c16 * 8);
    }
}

// ---------------------------------------------------------------------------
// Tensor-core GEMM: C[M,N] = A[M,K] @ B[N,K]^T   (both K-major, bf16 hi/lo)
// 16 warps: warp grid 2(M) x 8(N), warp tile 64x32.
// MODE 0: fp32 out ; MODE 1: split bf16 hi/lo out (row-major) ;
// MODE 2: split bf16 out, transposed per-batch into [b][n][m%SEQ] (Vt).
// ---------------------------------------------------------------------------
template <int MODE, bool RELU, bool BIAS>
__global__ __launch_bounds__(THREADS, 1)
void tc_gemm(const __nv_bfloat16* __restrict__ Ah, const __nv_bfloat16* __restrict__ Al,
             const __nv_bfloat16* __restrict__ Bh, const __nv_bfloat16* __restrict__ Bl,
             const float* __restrict__ bias,
             float* __restrict__ Cf,
             __nv_bfloat16* __restrict__ Ch, __nv_bfloat16* __restrict__ Cl,
             int K, int ldc, long long sA, long long sB, long long sC)
{
    extern __shared__ char smem[];
    const uint32_t su = smem_u32(smem);
    const int tid  = threadIdx.x;
    const int lane = tid & 31;
    const int wid  = tid >> 5;
    const int warp_m = (wid & 1) * 64;
    const int warp_n = (wid >> 1) * 32;
    const int bm = blockIdx.y * BM;
    const int bn = blockIdx.x * BN;
    const int z  = blockIdx.z;
    Ah += (long long)z * sA;  Al += (long long)z * sA;
    Bh += (long long)z * sB;  Bl += (long long)z * sB;

    float acc[4][4][4];
#pragma unroll
    for (int i = 0; i < 4; i++)
#pragma unroll
        for (int j = 0; j < 4; j++)
#pragma unroll
            for (int k = 0; k < 4; k++) acc[i][j][k] = 0.0f;

    const int nc = K / KC;

    load_stage(su, Ah, Al, Bh, Bl, bm, bn, K, 0, tid);
    asm volatile("cp.async.commit_group;" ::: "memory");
    load_stage(su + STAGE_BYTES, Ah, Al, Bh, Bl, bm, bn, K, KC, tid);
    asm volatile("cp.async.commit_group;" ::: "memory");

    // per-lane ldmatrix addressing components
    const int arow  = ((lane >> 3) & 1) * 8 + (lane & 7);  // row within 16-row frag
    const int chalf = lane >> 4;                           // k-half (16B chunk)
    const int swz   = lane & 7;

    for (int i = 0; i < nc; i++) {
        if (i + 1 < nc) asm volatile("cp.async.wait_group 1;" ::: "memory");
        else            asm volatile("cp.async.wait_group 0;" ::: "memory");
        __syncthreads();

        const uint32_t sb = su + (uint32_t)(i & 1) * STAGE_BYTES;
        const uint32_t aRow = sb + (uint32_t)(warp_m + arow) * 128u;
        const uint32_t bRow = sb + (uint32_t)(warp_n + arow) * 128u;

#pragma unroll
        for (int ks = 0; ks < 4; ks++) {
            const uint32_t cb = (uint32_t)(((ks * 2 + chalf) ^ swz) << 4);
            // B fragments for this warp's 32-wide N slice (hi+lo = 16 regs).
            uint32_t fbh[2][4], fbl[2][4];
#pragma unroll
            for (int jn = 0; jn < 2; jn++) {
                LDSM4(fbh[jn], bRow + OFF_BH + jn * 2048u + cb);
                LDSM4(fbl[jn], bRow + OFF_BL + jn * 2048u + cb);
            }
#pragma unroll
            for (int im = 0; im < 4; im++) {
                uint32_t fah[4], fal[4];
                LDSM4(fah, aRow + OFF_AH + im * 2048u + cb);
                LDSM4(fal, aRow + OFF_AL + im * 2048u + cb);
                // Pass 1: hi*hi
#pragma unroll
                for (int jn = 0; jn < 2; jn++) {
                    MMA(acc[im][2 * jn],     fah, fbh[jn][0], fbh[jn][2]);
                    MMA(acc[im][2 * jn + 1], fah, fbh[jn][1], fbh[jn][3]);
                }
                // Pass 2: hi*lo
#pragma unroll
                for (int jn = 0; jn < 2; jn++) {
                    MMA(acc[im][2 * jn],     fah, fbl[jn][0], fbl[jn][2]);
                    MMA(acc[im][2 * jn + 1], fah, fbl[jn][1], fbl[jn][3]);
                }
                // Pass 3: lo*hi
#pragma unroll
                for (int jn = 0; jn < 2; jn++) {
                    MMA(acc[im][2 * jn],     fal, fbh[jn][0], fbh[jn][2]);
                    MMA(acc[im][2 * jn + 1], fal, fbh[jn][1], fbh[jn][3]);
                }
            }
        }
        __syncthreads();
        if (i + 2 < nc) {
            load_stage(su + (uint32_t)(i & 1) * STAGE_BYTES,
                       Ah, Al, Bh, Bl, bm, bn, K, (i + 2) * KC, tid);
            asm volatile("cp.async.commit_group;" ::: "memory");
        }
    }

    // ---- epilogue: regs -> smem stage (bias/relu/convert) -> coalesced gmem ----
    uint32_t* stage = (uint32_t*)smem;
#pragma unroll
    for (int im = 0; im < 4; im++) {
#pragma unroll
        for (int j8 = 0; j8 < 4; j8++) {
            int r0 = warp_m + im * 16 + (lane >> 2);
            int c0 = warp_n + j8 * 8 + (lane & 3) * 2;
#pragma unroll
            for (int half = 0; half < 2; half++) {
                int r = r0 + half * 8;
#pragma unroll
                for (int cc = 0; cc < 2; cc++) {
                    float v = acc[im][j8][half * 2 + cc];
                    int c = c0 + cc;
                    if (BIAS) v += bias[bn + c];
                    if (RELU) v = fmaxf(v, 0.0f);
                    uint32_t w;
                    if (MODE == 0) {
                        w = __float_as_uint(v);
                    } else {
                        __nv_bfloat16 h = __float2bfloat16_rn(v);
                        float hf = __bfloat162float(h);
                        __nv_bfloat16 l = __float2bfloat16_rn(v - hf);
                        w = (uint32_t)__bfloat16_as_ushort(h) |
                            ((uint32_t)__bfloat16_as_ushort(l) << 16);
                    }
                    stage[r * EP_LD + c] = w;
                }
            }
        }
    }
    __syncthreads();

    if (MODE == 0) {
        float* Cp = Cf + (long long)z * sC;
#pragma unroll 4
        for (int k2 = 0; k2 < 64; k2++) {
            int idx = tid + k2 * THREADS;
            int r = idx >> 8, c = idx & 255;
            Cp[(long long)(bm + r) * ldc + bn + c] =
                __uint_as_float(stage[r * EP_LD + c]);
        }
    } else if (MODE == 1) {
        __nv_bfloat16* ChP = Ch + (long long)z * sC;
        __nv_bfloat16* ClP = Cl + (long long)z * sC;
#pragma unroll 4
        for (int k2 = 0; k2 < 32; k2++) {
            int p = tid + k2 * THREADS;
            int r = p >> 7, cp2 = (p & 127) * 2;
            uint32_t w0 = stage[r * EP_LD + cp2];
            uint32_t w1 = stage[r * EP_LD + cp2 + 1];
            uint32_t hw = (w0 & 0xFFFFu) | (w1 << 16);
            uint32_t lw = (w0 >> 16) | (w1 & 0xFFFF0000u);
            long long o = (long long)(bm + r) * ldc + bn + cp2;
            *(uint32_t*)(ChP + o) = hw;
            *(uint32_t*)(ClP + o) = lw;
        }
    } else {
        // Transposed split store: Vt[b][d][s], b = bm/SEQ, d = bn+c, s = bm%SEQ+r
        long long ob = (long long)(bm >> 11) * ((long long)DIM * SEQ);
        int sbase = bm & (SEQ - 1);
#pragma unroll 1
        for (int cc = 0; cc < 16; cc++) {
            int c = (tid >> 5) + cc * 16;
#pragma unroll
            for (int rr = 0; rr < 4; rr++) {
                int r = (tid & 31) + rr * 32;
                uint32_t w = stage[r * EP_LD + c];
                long long o = ob + (long long)(bn + c) * SEQ + sbase + r;
                Ch[o] = __ushort_as_bfloat16((unsigned short)(w & 0xFFFF));
                Cl[o] = __ushort_as_bfloat16((unsigned short)(w >> 16));
            }
        }
    }
}

// ------------- fp32 -> bf16 hi/lo split (single fused launch) --------------
// Segments (in 1024-element blocks): q,k,v = 8192 blocks each; w = 1024 each.
__global__ __launch_bounds__(256)
void split_all_kernel(const float* __restrict__ q, const float* __restrict__ k,
                      const float* __restrict__ v, const float* __restrict__ wq,
                      const float* __restrict__ wk, const float* __restrict__ wv,
                      __nv_bfloat16* __restrict__ qh, __nv_bfloat16* __restrict__ ql,
                      __nv_bfloat16* __restrict__ kh, __nv_bfloat16* __restrict__ kl,
                      __nv_bfloat16* __restrict__ vh, __nv_bfloat16* __restrict__ vl,
                      __nv_bfloat16* __restrict__ wqh, __nv_bfloat16* __restrict__ wql,
                      __nv_bfloat16* __restrict__ wkh, __nv_bfloat16* __restrict__ wkl,
                      __nv_bfloat16* __restrict__ wvh, __nv_bfloat16* __restrict__ wvl)
{
    int b = blockIdx.x;
    const float* x;
    __nv_bfloat16 *h, *l;
    int off;
    if      (b < 8192)  { x = q;  h = qh;  l = ql;  off = b; }
    else if (b < 16384) { x = k;  h = kh;  l = kl;  off = b - 8192; }
    else if (b < 24576) { x = v;  h = vh;  l = vl;  off = b - 16384; }
    else if (b < 25600) { x = wq; h = wqh; l = wql; off = b - 24576; }
    else if (b < 26624) { x = wk; h = wkh; l = wkl; off = b - 25600; }
    else                { x = wv; h = wvh; l = wvl; off = b - 26624; }

    int i = off * 1024 + threadIdx.x * 4;
    float4 val = *(const float4*)(x + i);
    float vv[4] = {val.x, val.y, val.z, val.w};
    unsigned short hs[4], ls[4];
#pragma unroll
    for (int j = 0; j < 4; j++) {
        __nv_bfloat16 hb = __float2bfloat16_rn(vv[j]);
        float hf = __bfloat162float(hb);
        __nv_bfloat16 lb = __float2bfloat16_rn(vv[j] - hf);
        hs[j] = __bfloat16_as_ushort(hb);
        ls[j] = __bfloat16_as_ushort(lb);
    }
    uint2 hw = make_uint2((uint32_t)hs[0] | ((uint32_t)hs[1] << 16),
                          (uint32_t)hs[2] | ((uint32_t)hs[3] << 16));
    uint2 lw = make_uint2((uint32_t)ls[0] | ((uint32_t)ls[1] << 16),
                          (uint32_t)ls[2] | ((uint32_t)ls[3] << 16));
    *(uint2*)(h + i) = hw;
    *(uint2*)(l + i) = lw;
}

// ---------------------------------------------------------------------------
extern "C" void kernel_launch(void* const* d_in, const int* in_sizes, int n_in,
                              void* d_out, int out_size)
{
    const float* queries = (const float*)d_in[0];
    const float* keys    = (const float*)d_in[1];
    const float* values  = (const float*)d_in[2];
    const float* Wq      = (const float*)d_in[3];
    const float* bq      = (const float*)d_in[4];
    const float* Wk      = (const float*)d_in[5];
    const float* bk      = (const float*)d_in[6];
    const float* Wv      = (const float*)d_in[7];
    const float* bv      = (const float*)d_in[8];
    float* out = (float*)d_out;

    __nv_bfloat16 *qih, *qil, *kih, *kil, *vih, *vil;
    __nv_bfloat16 *wqh, *wql, *wkh, *wkl, *wvh, *wvl;
    __nv_bfloat16 *Qh, *Ql, *Kh, *Kl, *Vth, *Vtl, *Sh, *Sl;
    cudaGetSymbolAddress((void**)&qih, g_qi_h); cudaGetSymbolAddress((void**)&qil, g_qi_l);
    cudaGetSymbolAddress((void**)&kih, g_ki_h); cudaGetSymbolAddress((void**)&kil, g_ki_l);
    cudaGetSymbolAddress((void**)&vih, g_vi_h); cudaGetSymbolAddress((void**)&vil, g_vi_l);
    cudaGetSymbolAddress((void**)&wqh, g_wq_h); cudaGetSymbolAddress((void**)&wql, g_wq_l);
    cudaGetSymbolAddress((void**)&wkh, g_wk_h); cudaGetSymbolAddress((void**)&wkl, g_wk_l);
    cudaGetSymbolAddress((void**)&wvh, g_wv_h); cudaGetSymbolAddress((void**)&wvl, g_wv_l);
    cudaGetSymbolAddress((void**)&Qh,  g_Q_h);  cudaGetSymbolAddress((void**)&Ql,  g_Q_l);
    cudaGetSymbolAddress((void**)&Kh,  g_K_h);  cudaGetSymbolAddress((void**)&Kl,  g_K_l);
    cudaGetSymbolAddress((void**)&Vth, g_Vt_h); cudaGetSymbolAddress((void**)&Vtl, g_Vt_l);
    cudaGetSymbolAddress((void**)&Sh,  g_S_h);  cudaGetSymbolAddress((void**)&Sl,  g_S_l);

    cudaFuncSetAttribute(tc_gemm<1, false, true>,
                         cudaFuncAttributeMaxDynamicSharedMemorySize, SMEM_TOTAL);
    cudaFuncSetAttribute(tc_gemm<2, false, true>,
                         cudaFuncAttributeMaxDynamicSharedMemorySize, SMEM_TOTAL);
    cudaFuncSetAttribute(tc_gemm<1, true, false>,
                         cudaFuncAttributeMaxDynamicSharedMemorySize, SMEM_TOTAL);
    cudaFuncSetAttribute(tc_gemm<0, false, false>,
                         cudaFuncAttributeMaxDynamicSharedMemorySize, SMEM_TOTAL);

    // 0) split inputs + weights into bf16 hi/lo (one fused launch)
    split_all_kernel<<<27648, 256>>>(queries, keys, values, Wq, Wk, Wv,
                                     qih, qil, kih, kil, vih, vil,
                                     wqh, wql, wkh, wkl, wvh, wvl);

    const int Mproj = BATCH * SEQ;       // 8192
    dim3 blk(THREADS);

    // 1) projections (M=8192, N=1024, K=1024)
    dim3 gp(DIM / BN, Mproj / BM, 1);
    tc_gemm<1, false, true><<<gp, blk, SMEM_TOTAL>>>(
        qih, qil, wqh, wql, bq, nullptr, Qh, Ql, DIM, DIM, 0, 0, 0);
    tc_gemm<1, false, true><<<gp, blk, SMEM_TOTAL>>>(
        kih, kil, wkh, wkl, bk, nullptr, Kh, Kl, DIM, DIM, 0, 0, 0);
    tc_gemm<2, false, true><<<gp, blk, SMEM_TOTAL>>>(
        vih, vil, wvh, wvl, bv, nullptr, Vth, Vtl, DIM, 0, 0, 0, 0);

    // 2) scores: relu(Q @ K^T) per batch (M=2048, N=2048, K=1024)
    dim3 gs(SEQ / BN, SEQ / BM, BATCH);
    tc_gemm<1, true, false><<<gs, blk, SMEM_TOTAL>>>(
        Qh, Ql, Kh, Kl, nullptr, nullptr, Sh, Sl, DIM, SEQ,
        (long long)SEQ * DIM, (long long)SEQ * DIM, (long long)SEQ * SEQ);

    // 3) output: Sc @ Vt^T per batch (M=2048, N=1024, K=2048)
    dim3 go(DIM / BN, SEQ / BM, BATCH);
    tc_gemm<0, false, false><<<go, blk, SMEM_TOTAL>>>(
        Sh, Sl, Vth, Vtl, nullptr, out, nullptr, nullptr, SEQ, DIM,
        (long long)SEQ * SEQ, (long long)DIM * SEQ, (long long)SEQ * DIM);

    (void)in_sizes; (void)n_in; (void)out_size;
}